// round 4
// baseline (speedup 1.0000x reference)
#include <cuda_runtime.h>
#include <cstdint>

#define N_NODES 100000
#define N_EDGES 1600000
#define NCOL 64      // 10 one-hot + 54 mlp
#define HID 128
#define MAXB 128     // max breakpoints
#define MAXSEG 129   // MAXB + 1

// -------- device-global scratch (allowed; no runtime allocation) --------
__device__ float g_bnd[MAXB];           // sorted breakpoints, padded +INF
__device__ int   g_nb;                  // number of valid breakpoints
__device__ int   g_is64;                // edge_index stored as int64?
__device__ __align__(16) float g_A[MAXSEG * NCOL];   // per-segment slope  (cols 0..9 zero)
__device__ __align__(16) float g_B[MAXSEG * NCOL];   // per-segment offset (cols 0..9 zero)
__device__ __align__(16) float g_d[(size_t)N_NODES * NCOL];  // segment sums -> reciprocals

// -------- detect int64 vs int32 edge_index layout --------
__global__ void k_detect(const int* __restrict__ eip) {
    // int64 little-endian with values < 2^31 -> all odd 32-bit words are 0.
    // int32 layout -> odd words are src[1],src[3],... (random in [0,1e5)).
    unsigned m = __ballot_sync(0xffffffffu, eip[2 * threadIdx.x + 1] != 0);
    if (threadIdx.x == 0) g_is64 = (m == 0) ? 1 : 0;
}

// -------- zero the accumulator --------
__global__ void k_zero() {
    unsigned i = blockIdx.x * blockDim.x + threadIdx.x;
    if (i < (unsigned)(N_NODES * (NCOL / 4)))
        ((float4*)g_d)[i] = make_float4(0.f, 0.f, 0.f, 0.f);
}

// -------- breakpoints of relu(dist*W1[j] + b1[j]) in (0, 10), sorted --------
__global__ void k_breaks(const float* __restrict__ W1, const float* __restrict__ b1) {
    __shared__ float t[HID];
    __shared__ int   vld[HID];
    __shared__ float sorted[HID];
    int j = threadIdx.x;                 // 128 threads
    float w = W1[j], b = b1[j];
    float tj = -b / w;
    int v = (w != 0.f) && (tj > 0.f) && (tj < 10.f);   // NaN excluded by compares
    t[j] = tj;
    vld[j] = v;
    sorted[j] = __int_as_float(0x7f800000);            // +INF padding
    __syncthreads();
    int rank = 0, nb = 0;
    for (int i = 0; i < HID; i++) {
        if (vld[i]) {
            nb++;
            if (t[i] < t[j] || (t[i] == t[j] && i < j)) rank++;
        }
    }
    __syncthreads();
    if (v) sorted[rank] = t[j];
    __syncthreads();
    g_bnd[j] = sorted[j];
    if (j == 0) g_nb = nb;
}

// -------- per-segment affine coefficients: w_mlp[k] = relu(A*dist + B) --------
__global__ void k_coeffs(const float* __restrict__ W1, const float* __restrict__ b1,
                         const float* __restrict__ W2, const float* __restrict__ b2) {
    int seg = blockIdx.x;        // 0..MAXSEG-1
    int col = threadIdx.x;       // 0..63
    int nb = g_nb;
    float A = 0.f, B = 0.f;
    if (seg <= nb && col >= 10) {
        int m = col - 10;        // 0..53
        float lo = (seg == 0) ? 0.f  : g_bnd[seg - 1];
        float hi = (seg == nb) ? 10.f : g_bnd[seg];
        float x  = 0.5f * (lo + hi);   // interior point -> exact active set
        B = b2[m];
        #pragma unroll 4
        for (int j = 0; j < HID; j++) {
            float w1 = W1[j], bb = b1[j];
            if (fmaf(w1, x, bb) > 0.f) {
                float w2 = W2[j * 54 + m];
                A = fmaf(w1, w2, A);
                B = fmaf(bb, w2, B);
            }
        }
    }
    g_A[seg * NCOL + col] = A;
    g_B[seg * NCOL + col] = B;
}

// -------- invert accumulator: d -> (d==0 ? 0 : 1/d) --------
__global__ void k_invert() {
    unsigned i = blockIdx.x * blockDim.x + threadIdx.x;
    if (i < (unsigned)(N_NODES * (NCOL / 4))) {
        float4 v = ((float4*)g_d)[i];
        v.x = (v.x != 0.f) ? 1.f / v.x : 0.f;
        v.y = (v.y != 0.f) ? 1.f / v.y : 0.f;
        v.z = (v.z != 0.f) ? 1.f / v.z : 0.f;
        v.w = (v.w != 0.f) ? 1.f / v.w : 0.f;
        ((float4*)g_d)[i] = v;
    }
}

// -------- main: SCATTER (atomic segment-sum) / GATHER (normalize + write) --------
// Coefficient tables read from global via __ldg: 66 KB, fully L1-resident,
// broadcast-coalesced (the 16 threads of one edge share `pos`). Only the
// 512 B breakpoint array lives in shared memory (7 dependent loads/thread).
template <bool SCATTER>
__global__ void __launch_bounds__(256)
k_main(const float* __restrict__ edge_attr, const int* __restrict__ eip,
       float4* __restrict__ out) {
    __shared__ float sbnd[MAXB];
    if (threadIdx.x < MAXB) sbnd[threadIdx.x] = g_bnd[threadIdx.x];
    __syncthreads();

    const int is64 = g_is64;
    const unsigned total  = (unsigned)N_EDGES * 16u;
    const unsigned stride = gridDim.x * 256u;
    for (unsigned idx = blockIdx.x * 256u + threadIdx.x; idx < total; idx += stride) {
        int e = (int)(idx >> 4);
        int c = (int)(idx & 15u);
        float dist = __ldg(edge_attr + e);
        int src = is64 ? __ldg(eip + 2 * e) : __ldg(eip + e);

        // branchless lower-bound over 128 padded boundaries: pos = #(bnd < dist)
        int pos = 0;
        #pragma unroll
        for (int s = 64; s; s >>= 1)
            if (sbnd[pos + s - 1] < dist) pos += s;
        pos += (sbnd[pos] < dist) ? 1 : 0;     // pos in [0, MAXB] -> segment id

        const float4 a4 = __ldg((const float4*)(g_A + pos * NCOL + c * 4));
        const float4 b4 = __ldg((const float4*)(g_B + pos * NCOL + c * 4));
        float4 w;
        w.x = fmaxf(fmaf(a4.x, dist, b4.x), 0.f);
        w.y = fmaxf(fmaf(a4.y, dist, b4.y), 0.f);
        w.z = fmaxf(fmaf(a4.z, dist, b4.z), 0.f);
        w.w = fmaxf(fmaf(a4.w, dist, b4.w), 0.f);

        int bucket = (int)dist;                 // dist > 0
        if (bucket > 9) bucket = 9;
        if ((bucket >> 2) == c) {               // inject one-hot
            int lb = bucket & 3;
            if      (lb == 0) w.x += 1.f;
            else if (lb == 1) w.y += 1.f;
            else if (lb == 2) w.z += 1.f;
            else              w.w += 1.f;
        }

        if (SCATTER) {
            if ((w.x != 0.f) | (w.y != 0.f) | (w.z != 0.f) | (w.w != 0.f)) {
                float* dst = g_d + src * NCOL + c * 4;
                asm volatile("red.global.add.v4.f32 [%0], {%1,%2,%3,%4};"
                             :: "l"(dst), "f"(w.x), "f"(w.y), "f"(w.z), "f"(w.w)
                             : "memory");
            }
        } else {
            const float4 di = __ldg((const float4*)g_d + src * (NCOL / 4) + c);
            float4 o = make_float4(w.x * di.x, w.y * di.y, w.z * di.z, w.w * di.w);
            __stcs(out + idx, o);               // streaming: don't evict d from L2
        }
    }
}

extern "C" void kernel_launch(void* const* d_in, const int* in_sizes, int n_in,
                              void* d_out, int out_size) {
    // metadata order: x, edge_index, edge_attr, W1, b1, W2, b2
    const int*   eip       = (const int*)d_in[1];
    const float* edge_attr = (const float*)d_in[2];
    const float* W1        = (const float*)d_in[3];
    const float* b1        = (const float*)d_in[4];
    const float* W2        = (const float*)d_in[5];
    const float* b2        = (const float*)d_in[6];
    (void)in_sizes; (void)n_in; (void)out_size;

    const int nq4 = N_NODES * (NCOL / 4);      // 1.6M float4s in d

    k_detect<<<1, 32>>>(eip);
    k_zero<<<(nq4 + 255) / 256, 256>>>();
    k_breaks<<<1, HID>>>(W1, b1);
    k_coeffs<<<MAXSEG, NCOL>>>(W1, b1, W2, b2);
    k_main<true><<<1184, 256>>>(edge_attr, eip, nullptr);
    k_invert<<<(nq4 + 255) / 256, 256>>>();
    k_main<false><<<1184, 256>>>(edge_attr, eip, (float4*)d_out);
}

// round 6
// speedup vs baseline: 1.2470x; 1.2470x over previous
#include <cuda_runtime.h>
#include <cstdint>

#define N_NODES 100000
#define N_EDGES 1600000
#define NCOL 64      // 10 one-hot + 54 mlp
#define HID 128
#define MAXB 128     // max breakpoints
#define MAXSEG 129   // MAXB + 1
#define LUTN 1024

// -------- device-global scratch (allowed; no runtime allocation) --------
__device__ float g_bnd[MAXB + 1];       // sorted breakpoints, padded +INF (incl. [128])
__device__ int   g_nb;                  // number of valid breakpoints
__device__ int   g_is64;                // edge_index stored as int64?
__device__ unsigned char g_lut[LUTN];   // dist-cell -> lower bound on segment id
__device__ __align__(16) float g_A[MAXSEG * NCOL];   // per-segment slope  (cols 0..9 zero)
__device__ __align__(16) float g_B[MAXSEG * NCOL];   // per-segment offset (cols 0..9 zero)
__device__ __align__(16) float g_d[(size_t)N_NODES * NCOL];  // segment sums -> reciprocals

// -------- init: detect idx dtype, sorted breakpoints, segment LUT --------
__global__ void k_init(const int* __restrict__ eip,
                       const float* __restrict__ W1, const float* __restrict__ b1) {
    __shared__ float t[HID];
    __shared__ int   vld[HID];
    __shared__ float sorted[HID + 1];
    int j = threadIdx.x;                 // 128 threads

    if (j < 32) {
        // int64 little-endian with values < 2^31 -> all odd 32-bit words are 0.
        unsigned m = __ballot_sync(0xffffffffu, eip[2 * j + 1] != 0);
        if (j == 0) g_is64 = (m == 0) ? 1 : 0;
    }

    float w = W1[j], b = b1[j];
    float tj = -b / w;
    int v = (w != 0.f) && (tj > 0.f) && (tj < 10.f);   // NaN excluded by compares
    t[j] = tj;
    vld[j] = v;
    sorted[j] = __int_as_float(0x7f800000);            // +INF padding
    if (j == 0) sorted[HID] = __int_as_float(0x7f800000);
    __syncthreads();
    int rank = 0, nb = 0;
    for (int i = 0; i < HID; i++) {
        if (vld[i]) {
            nb++;
            if (t[i] < t[j] || (t[i] == t[j] && i < j)) rank++;
        }
    }
    __syncthreads();
    if (v) sorted[rank] = t[j];
    __syncthreads();
    g_bnd[j] = sorted[j];
    if (j == 0) { g_bnd[HID] = sorted[HID]; g_nb = nb; }

    // LUT: conservative lower bound of segment id at each cell start.
    // Deflated threshold guarantees we only UNDERestimate (advance loop fixes it).
    #pragma unroll
    for (int k = 0; k < LUTN / HID; k++) {
        int cell = j * (LUTN / HID) + k;
        float thresh = (float)cell * (10.0f / LUTN) * 0.999999f - 1e-6f;
        int cnt = 0;
        for (int i = 0; i < HID; i++)
            cnt += (sorted[i] < thresh) ? 1 : 0;
        g_lut[cell] = (unsigned char)cnt;
    }
}

// -------- zero the accumulator --------
__global__ void k_zero() {
    unsigned i = blockIdx.x * blockDim.x + threadIdx.x;
    if (i < (unsigned)(N_NODES * (NCOL / 4)))
        ((float4*)g_d)[i] = make_float4(0.f, 0.f, 0.f, 0.f);
}

// -------- per-segment affine coefficients: w_mlp[k] = relu(A*dist + B) --------
// 33 blocks x 256 threads; each block handles 4 segments, weights staged in smem.
__global__ void __launch_bounds__(256) k_coeffs(
        const float* __restrict__ W1, const float* __restrict__ b1,
        const float* __restrict__ W2, const float* __restrict__ b2) {
    __shared__ float sW1[HID], sb1[HID], sb2[54];
    __shared__ float sW2[HID * 54];
    for (int i = threadIdx.x; i < HID * 54; i += 256) sW2[i] = W2[i];
    if (threadIdx.x < HID) { sW1[threadIdx.x] = W1[threadIdx.x]; sb1[threadIdx.x] = b1[threadIdx.x]; }
    if (threadIdx.x < 54)  sb2[threadIdx.x] = b2[threadIdx.x];
    __syncthreads();

    int seg = blockIdx.x * 4 + (threadIdx.x >> 6);   // 0..131
    int col = threadIdx.x & 63;                      // 0..63
    if (seg >= MAXSEG) return;
    int nb = g_nb;
    float A = 0.f, B = 0.f;
    if (seg <= nb && col >= 10) {
        int m = col - 10;        // 0..53
        float lo = (seg == 0) ? 0.f  : g_bnd[seg - 1];
        float hi = (seg == nb) ? 10.f : g_bnd[seg];
        float x  = 0.5f * (lo + hi);   // interior point -> exact active set
        B = sb2[m];
        #pragma unroll 8
        for (int j = 0; j < HID; j++) {
            float w1 = sW1[j], bb = sb1[j];
            if (fmaf(w1, x, bb) > 0.f) {
                float w2 = sW2[j * 54 + m];
                A = fmaf(w1, w2, A);
                B = fmaf(bb, w2, B);
            }
        }
    }
    g_A[seg * NCOL + col] = A;
    g_B[seg * NCOL + col] = B;
}

// -------- invert accumulator: d -> (d==0 ? 0 : 1/d) --------
__global__ void k_invert() {
    unsigned i = blockIdx.x * blockDim.x + threadIdx.x;
    if (i < (unsigned)(N_NODES * (NCOL / 4))) {
        float4 v = ((float4*)g_d)[i];
        v.x = (v.x != 0.f) ? 1.f / v.x : 0.f;
        v.y = (v.y != 0.f) ? 1.f / v.y : 0.f;
        v.z = (v.z != 0.f) ? 1.f / v.z : 0.f;
        v.w = (v.w != 0.f) ? 1.f / v.w : 0.f;
        ((float4*)g_d)[i] = v;
    }
}

// -------- main: SCATTER (atomic segment-sum) / GATHER (normalize + write) --------
// Segment lookup: 1 smem LUT byte + short exact advance (replaces binary search).
// Coefficient tables stay in global via __ldg: 66 KB, L1-resident, broadcast
// across the 16 threads of one edge (they share `pos`).
template <bool SCATTER>
__global__ void __launch_bounds__(256)
k_main(const float* __restrict__ edge_attr, const int* __restrict__ eip,
       float4* __restrict__ out) {
    __shared__ float sbnd[MAXB + 1];
    __shared__ unsigned char slut[LUTN];
    if (threadIdx.x < MAXB + 1) sbnd[threadIdx.x] = g_bnd[threadIdx.x];
    for (int i = threadIdx.x; i < LUTN; i += 256) slut[i] = g_lut[i];
    __syncthreads();

    const int is64 = g_is64;
    const unsigned total  = (unsigned)N_EDGES * 16u;
    const unsigned stride = gridDim.x * 256u;
    for (unsigned idx = blockIdx.x * 256u + threadIdx.x; idx < total; idx += stride) {
        int e = (int)(idx >> 4);
        int c = (int)(idx & 15u);
        float dist = __ldg(edge_attr + e);
        int src = is64 ? __ldg(eip + 2 * e) : __ldg(eip + e);

        // segment id = #(bnd < dist): LUT lower bound + exact advance
        int cell = (int)(dist * (LUTN / 10.0f));
        cell = (cell < 0) ? 0 : ((cell > LUTN - 1) ? LUTN - 1 : cell);
        int pos = slut[cell];
        while (sbnd[pos] < dist) pos++;          // bnd padded +INF at [128]

        const float4 a4 = __ldg((const float4*)(g_A + pos * NCOL + c * 4));
        const float4 b4 = __ldg((const float4*)(g_B + pos * NCOL + c * 4));
        float4 w;
        w.x = fmaxf(fmaf(a4.x, dist, b4.x), 0.f);
        w.y = fmaxf(fmaf(a4.y, dist, b4.y), 0.f);
        w.z = fmaxf(fmaf(a4.z, dist, b4.z), 0.f);
        w.w = fmaxf(fmaf(a4.w, dist, b4.w), 0.f);

        int bucket = (int)dist;                 // dist > 0
        if (bucket > 9) bucket = 9;
        if ((bucket >> 2) == c) {               // inject one-hot
            int lb = bucket & 3;
            if      (lb == 0) w.x += 1.f;
            else if (lb == 1) w.y += 1.f;
            else if (lb == 2) w.z += 1.f;
            else              w.w += 1.f;
        }

        if (SCATTER) {
            if ((w.x != 0.f) | (w.y != 0.f) | (w.z != 0.f) | (w.w != 0.f)) {
                float* dst = g_d + src * NCOL + c * 4;
                asm volatile("red.global.add.v4.f32 [%0], {%1,%2,%3,%4};"
                             :: "l"(dst), "f"(w.x), "f"(w.y), "f"(w.z), "f"(w.w)
                             : "memory");
            }
        } else {
            const float4 di = __ldg((const float4*)g_d + src * (NCOL / 4) + c);
            float4 o = make_float4(w.x * di.x, w.y * di.y, w.z * di.z, w.w * di.w);
            __stcs(out + idx, o);               // streaming: don't evict d from L2
        }
    }
}

extern "C" void kernel_launch(void* const* d_in, const int* in_sizes, int n_in,
                              void* d_out, int out_size) {
    // metadata order: x, edge_index, edge_attr, W1, b1, W2, b2
    const int*   eip       = (const int*)d_in[1];
    const float* edge_attr = (const float*)d_in[2];
    const float* W1        = (const float*)d_in[3];
    const float* b1        = (const float*)d_in[4];
    const float* W2        = (const float*)d_in[5];
    const float* b2        = (const float*)d_in[6];
    (void)in_sizes; (void)n_in; (void)out_size;

    const int nq4 = N_NODES * (NCOL / 4);      // 1.6M float4s in d

    k_init<<<1, HID>>>(eip, W1, b1);
    k_zero<<<(nq4 + 255) / 256, 256>>>();
    k_coeffs<<<33, 256>>>(W1, b1, W2, b2);
    k_main<true><<<1184, 256>>>(edge_attr, eip, nullptr);
    k_invert<<<(nq4 + 255) / 256, 256>>>();
    k_main<false><<<1184, 256>>>(edge_attr, eip, (float4*)d_out);
}